// round 7
// baseline (speedup 1.0000x reference)
#include <cuda_runtime.h>

#define SS 2048
#define RR 384

typedef unsigned long long ull;

// ---- device scratch (no allocs allowed) ----
__device__ float g_kv[RR * 16 * SS];     // [r][c][s]; c: 0-7 = k, 8-15 = v
__device__ float g_maskT[RR * SS];       // transposed mask [r][s]
__device__ float g_qpart[RR * 16 * 68];  // per-(r, s-block) partials
__device__ float g_o[RR * 64];           // attention output per r  [h*8+c]
__device__ float2 g_stats[SS * RR];      // per-row (mu, rstd), [s][r] layout
// LN-folded weights (kernel P)
__device__ float g_AW[16 * 64];          // [c][d] = g[d]*Wkv[d][c]
__device__ float g_S1kv[16];
__device__ float g_bkv[16];
__device__ float g_GW[64 * 64];          // [j][d] = g[d]*Wg[d][j]
__device__ float g_S1g[64];
__device__ float g_bG[64];               // bg[j] + sum_d b[d]*Wg[d][j]
__device__ float g_WoT[64 * 64];         // [d][j] = Wo[j][d]

// ---- packed fp32x2 helpers (Blackwell FFMA2) ----
__device__ __forceinline__ ull ffma2(ull a, ull b, ull c) {
    ull d;
    asm("fma.rn.f32x2 %0, %1, %2, %3;" : "=l"(d) : "l"(a), "l"(b), "l"(c));
    return d;
}
__device__ __forceinline__ float2 upk(ull v) {
    float2 f; asm("mov.b64 {%0,%1}, %2;" : "=f"(f.x), "=f"(f.y) : "l"(v)); return f;
}
__device__ __forceinline__ ull pk2(float lo, float hi) {
    ull r; asm("mov.b64 %0, {%1,%2};" : "=l"(r) : "f"(lo), "f"(hi)); return r;
}

// ---------------------------------------------------------------------------
// Kernel D: transpose mask [S][R] -> [R][S]
// ---------------------------------------------------------------------------
__global__ __launch_bounds__(256) void kernelD(const float* __restrict__ Mmask) {
    __shared__ float t[32][33];
    const int tx = threadIdx.x & 31, ty = threadIdx.x >> 5;
    const int r0 = blockIdx.x * 32, s0 = blockIdx.y * 32;
    #pragma unroll
    for (int k = 0; k < 32; k += 8)
        t[ty + k][tx] = Mmask[(s0 + ty + k) * RR + r0 + tx];
    __syncthreads();
    #pragma unroll
    for (int k = 0; k < 32; k += 8)
        g_maskT[(r0 + ty + k) * SS + s0 + tx] = t[tx][ty + k];
}

// ---------------------------------------------------------------------------
// Kernel P: fold LayerNorm gamma/beta into all weight matrices (tiny, once)
// ---------------------------------------------------------------------------
__global__ __launch_bounds__(256) void kernelP(
    const float* __restrict__ lng, const float* __restrict__ lnb,
    const float* __restrict__ Wk, const float* __restrict__ Wv,
    const float* __restrict__ Wg, const float* __restrict__ bg,
    const float* __restrict__ Wo)
{
    const int tid = threadIdx.x;
    for (int i = tid; i < 16 * 64; i += 256) {
        int c = i >> 6, d = i & 63;
        float w = (c < 8) ? Wk[d * 8 + c] : Wv[d * 8 + c - 8];
        g_AW[i] = lng[d] * w;
    }
    for (int i = tid; i < 64 * 64; i += 256) {
        int a = i >> 6, b = i & 63;
        g_GW[i]  = lng[b] * Wg[b * 64 + a];   // [j=a][d=b]
        g_WoT[i] = Wo[b * 64 + a];            // [d=a][j=b]
    }
    __syncthreads();
    if (tid < 16) {
        float s1 = 0.f, bb = 0.f;
        for (int d = 0; d < 64; ++d) {
            s1 += g_AW[tid * 64 + d];
            float w = (tid < 8) ? Wk[d * 8 + tid] : Wv[d * 8 + tid - 8];
            bb += lnb[d] * w;
        }
        g_S1kv[tid] = s1; g_bkv[tid] = bb;
    }
    if (tid >= 64 && tid < 128) {
        int j = tid - 64;
        float s1 = 0.f, bb = 0.f;
        for (int d = 0; d < 64; ++d) {
            s1 += g_GW[j * 64 + d];
            bb += lnb[d] * Wg[d * 64 + j];
        }
        g_S1g[j] = s1; g_bG[j] = bg[j] + bb;
    }
}

// ---------------------------------------------------------------------------
// Kernel A: rows-in-lanes LN (folded) + k/v projection + masked-q partials
// stores per-row (mu, rstd) to g_stats in [s][r] layout for kernelC
// ---------------------------------------------------------------------------
__global__ __launch_bounds__(128) void kernelA(const float* __restrict__ M) {
    __shared__ __align__(16) float stage[4][32][68];
    __shared__ __align__(16) float sAW[16][68];
    __shared__ float sS1[16], sbk[16];
    __shared__ float sQ[4][68];
    const int tid = threadIdx.x, w = tid >> 5, t = tid & 31;
    const int r = blockIdx.y;
    const int srow = blockIdx.x * 128 + w * 32;

    for (int i = tid; i < 16 * 64; i += 128) { int c = i >> 6, d = i & 63; sAW[c][d] = g_AW[i]; }
    if (tid < 16) { sS1[tid] = g_S1kv[tid]; sbk[tid] = g_bkv[tid]; }
    __syncthreads();

    const int cr = t >> 4, cc = (t & 15) * 4;
    #pragma unroll
    for (int i = 0; i < 16; ++i) {
        int rr = i * 2 + cr;
        *(float4*)&stage[w][rr][cc] =
            *(const float4*)&M[(((srow + rr) * RR) + r) * 64 + cc];
    }
    __syncwarp();

    ull xp[32];
    {
        const ulonglong2* rp = (const ulonglong2*)&stage[w][t][0];
        #pragma unroll
        for (int i = 0; i < 16; ++i) { ulonglong2 v = rp[i]; xp[2 * i] = v.x; xp[2 * i + 1] = v.y; }
    }
    float sum = 0.f, sq = 0.f;
    #pragma unroll
    for (int i = 0; i < 32; ++i) { float2 f = upk(xp[i]); sum += f.x + f.y; sq += f.x * f.x + f.y * f.y; }
    const float mu = sum * (1.f / 64.f);
    const float rstd = rsqrtf(sq * (1.f / 64.f) - mu * mu + 1e-5f);
    const int s = srow + t;
    const float mk = g_maskT[r * SS + s];
    g_stats[s * RR + r] = make_float2(mu, rstd);   // [s][r] layout for kernelC

    // k/v projection (LN folded)
    #pragma unroll
    for (int c = 0; c < 16; ++c) {
        const ulonglong2* wp_ = (const ulonglong2*)&sAW[c][0];
        ull a0 = 0ull, a1 = 0ull;
        #pragma unroll
        for (int i = 0; i < 16; ++i) {
            ulonglong2 v = wp_[i];
            a0 = ffma2(xp[2 * i], v.x, a0);
            a1 = ffma2(xp[2 * i + 1], v.y, a1);
        }
        float2 f0 = upk(a0), f1 = upk(a1);
        float dot = f0.x + f0.y + f1.x + f1.y;
        g_kv[((r * 16 + c) * SS) + s] = rstd * (dot - mu * sS1[c]) + sbk[c];
    }

    // masked-query partial rows -> reuse tile, then column-reduce
    {
        const float mkr = mk * rstd;
        const ull mp = pk2(mkr, mkr);
        float4* qr = (float4*)&stage[w][t][0];
        #pragma unroll
        for (int i = 0; i < 16; ++i) {
            float2 a = upk(ffma2(xp[2 * i], mp, 0ull));
            float2 b = upk(ffma2(xp[2 * i + 1], mp, 0ull));
            qr[i] = make_float4(a.x, a.y, b.x, b.y);
        }
        stage[w][t][64] = mkr * mu;  // Pmu contribution
        stage[w][t][65] = mk;        // Pc contribution
    }
    __syncwarp();
    {
        float ax = 0.f, ay = 0.f;
        #pragma unroll
        for (int rr = 0; rr < 32; ++rr) {
            float2 v = *(const float2*)&stage[w][rr][2 * t];
            ax += v.x; ay += v.y;
        }
        sQ[w][2 * t] = ax; sQ[w][2 * t + 1] = ay;
        if (t < 2) {
            float e = 0.f;
            #pragma unroll
            for (int rr = 0; rr < 32; ++rr) e += stage[w][rr][64 + t];
            sQ[w][64 + t] = e;
        }
    }
    __syncthreads();
    if (tid < 66) {
        float a = sQ[0][tid] + sQ[1][tid] + sQ[2][tid] + sQ[3][tid];
        g_qpart[(r * 16 + blockIdx.x) * 68 + tid] = a;
    }
}

// ---------------------------------------------------------------------------
// Kernel B: pooled q, two-pass streaming softmax over S (no logits buffer)
// ---------------------------------------------------------------------------
__global__ __launch_bounds__(256) void kernelB(
    const float* __restrict__ Wq, const float* __restrict__ lng,
    const float* __restrict__ lnb)
{
    __shared__ float sqa[68];
    __shared__ float sq[64];
    __shared__ float smax[8];
    __shared__ float red[8][80];
    const int tid = threadIdx.x, w = tid >> 5, t = tid & 31, r = blockIdx.x;

    if (tid < 66) {
        float a = 0.f;
        #pragma unroll
        for (int c = 0; c < 16; ++c) a += g_qpart[(r * 16 + c) * 68 + tid];
        sqa[tid] = a;
    }
    __syncthreads();
    if (tid < 64) {
        float Pmu = sqa[64], Pc = sqa[65];
        sqa[tid] = (lng[tid] * (sqa[tid] - Pmu) + lnb[tid] * Pc) / (Pc + 1e-10f);
    }
    __syncthreads();
    if (tid < 64) {
        float acc = 0.f;
        #pragma unroll
        for (int d = 0; d < 64; ++d) acc += sqa[d] * Wq[d * 64 + tid];
        sq[tid] = acc * 0.35355339059327373f;
    }
    __syncthreads();

    // pass 1: per-head max
    float mx[8];
    #pragma unroll
    for (int h = 0; h < 8; ++h) mx[h] = -3.0e38f;
    for (int s = tid; s < SS; s += 256) {
        float kk[8];
        #pragma unroll
        for (int c = 0; c < 8; ++c) kk[c] = g_kv[((r * 16 + c) * SS) + s];
        float bias = 1e9f * (g_maskT[r * SS + s] - 1.f);
        #pragma unroll
        for (int h = 0; h < 8; ++h) {
            float lg = bias;
            #pragma unroll
            for (int c = 0; c < 8; ++c) lg += sq[h * 8 + c] * kk[c];
            mx[h] = fmaxf(mx[h], lg);
        }
    }
    #pragma unroll
    for (int h = 0; h < 8; ++h) {
        #pragma unroll
        for (int o = 16; o > 0; o >>= 1) mx[h] = fmaxf(mx[h], __shfl_xor_sync(0xffffffffu, mx[h], o));
    }
    if (t < 8) red[w][t] = mx[t];
    __syncthreads();
    if (tid < 8) {
        float m = red[0][tid];
        #pragma unroll
        for (int ww = 1; ww < 8; ++ww) m = fmaxf(m, red[ww][tid]);
        smax[tid] = m;
    }
    __syncthreads();

    // pass 2: exp + weighted-v accumulation
    float Z[8];
    float acc[64];
    #pragma unroll
    for (int h = 0; h < 8; ++h) Z[h] = 0.f;
    #pragma unroll
    for (int i = 0; i < 64; ++i) acc[i] = 0.f;
    for (int s = tid; s < SS; s += 256) {
        float kk[8], vv[8];
        #pragma unroll
        for (int c = 0; c < 8; ++c) kk[c] = g_kv[((r * 16 + c) * SS) + s];
        #pragma unroll
        for (int c = 0; c < 8; ++c) vv[c] = g_kv[((r * 16 + 8 + c) * SS) + s];
        float bias = 1e9f * (g_maskT[r * SS + s] - 1.f);
        #pragma unroll
        for (int h = 0; h < 8; ++h) {
            float lg = bias;
            #pragma unroll
            for (int c = 0; c < 8; ++c) lg += sq[h * 8 + c] * kk[c];
            float e = __expf(lg - smax[h]);
            Z[h] += e;
            #pragma unroll
            for (int c = 0; c < 8; ++c) acc[h * 8 + c] += e * vv[c];
        }
    }
    #pragma unroll
    for (int i = 0; i < 64; ++i) {
        float v = acc[i];
        #pragma unroll
        for (int o = 16; o > 0; o >>= 1) v += __shfl_xor_sync(0xffffffffu, v, o);
        if (t == 0) red[w][i] = v;
    }
    #pragma unroll
    for (int h = 0; h < 8; ++h) {
        float v = Z[h];
        #pragma unroll
        for (int o = 16; o > 0; o >>= 1) v += __shfl_xor_sync(0xffffffffu, v, o);
        if (t == 0) red[w][64 + h] = v;
    }
    __syncthreads();
    if (tid < 72) {
        float v = 0.f;
        #pragma unroll
        for (int ww = 0; ww < 8; ++ww) v += red[ww][tid];
        red[0][tid] = v;
    }
    __syncthreads();
    if (tid < 64) g_o[r * 64 + tid] = red[0][tid] / red[0][64 + (tid >> 3)];
}

// ---------------------------------------------------------------------------
// Kernel C (hot): s-major tiling — warp tile = 32 consecutive r at ONE s,
// so every M read / out write is an 8KB CONTIGUOUS block. Col-per-lane
// compute: weights in registers, x/ghat rows broadcast from smem.
// grid (12, 128): block = r-chunk of 32, 16 s-values (4 warps x 4 iters).
// ---------------------------------------------------------------------------
__global__ __launch_bounds__(128) void kernelC(
    const float* __restrict__ M, const float* __restrict__ bo,
    float* __restrict__ outp)
{
    extern __shared__ __align__(16) float dyn[];
    const int tid = threadIdx.x, w = tid >> 5, t = tid & 31;
    const int r0 = blockIdx.x * 32;
    const int s0 = blockIdx.y * 16;
    float* xt = dyn + (w * 2 + 0) * (32 * 68);
    float* gt = dyn + (w * 2 + 1) * (32 * 68);
    float* so = dyn + 8 * (32 * 68);         // g_o slice [32 r][64]

    for (int i = tid; i < 2048; i += 128) so[i] = g_o[r0 * 64 + i];
    __syncthreads();

    // per-lane (column) constants: lane owns cols {2t, 2t+1} in both phases
    const float2 s1g = *(const float2*)&g_S1g[2 * t];
    const float2 bG2 = *(const float2*)&g_bG[2 * t];
    const float2 bo2 = *(const float2*)&bo[2 * t];

    ull gw[64];  // current-phase weights: [0..31] = col 2t, [32..63] = col 2t+1

    for (int it = 0; it < 4; ++it) {
        const int s = s0 + it * 4 + w;
        const float* Mbase = M + ((size_t)s * RR + r0) * 64;

        // stage 8KB contiguous: rows rr = r-offset, cols d
        #pragma unroll
        for (int i = 0; i < 16; ++i) {
            int f = i * 32 + t;                 // float4 index 0..511
            int rr = f >> 4, cc = (f & 15) * 4;
            *(float4*)&xt[rr * 68 + cc] = *(const float4*)&Mbase[f * 4];
        }
        *(float2*)&xt[t * 68 + 66] = g_stats[(size_t)s * RR + r0 + t];
        __syncwarp();

        // ---- gate phase ----
        {
            const ulonglong2* p0 = (const ulonglong2*)(g_GW + (2 * t) * 64);
            const ulonglong2* p1 = (const ulonglong2*)(g_GW + (2 * t + 1) * 64);
            #pragma unroll
            for (int i = 0; i < 16; ++i) {
                ulonglong2 v0 = p0[i], v1 = p1[i];
                gw[2 * i] = v0.x; gw[2 * i + 1] = v0.y;
                gw[32 + 2 * i] = v1.x; gw[32 + 2 * i + 1] = v1.y;
            }
        }
        for (int row = 0; row < 32; ++row) {
            const ulonglong2* xr = (const ulonglong2*)&xt[row * 68];
            ull a00 = 0ull, a01 = 0ull, a10 = 0ull, a11 = 0ull;
            #pragma unroll
            for (int i = 0; i < 16; ++i) {
                ulonglong2 xv = xr[i];
                a00 = ffma2(xv.x, gw[2 * i], a00);
                a01 = ffma2(xv.y, gw[2 * i + 1], a01);
                a10 = ffma2(xv.x, gw[32 + 2 * i], a10);
                a11 = ffma2(xv.y, gw[32 + 2 * i + 1], a11);
            }
            float2 st = *(const float2*)&xt[row * 68 + 66];
            float2 f;
            f = upk(a00); float d0 = f.x + f.y;
            f = upk(a01); d0 += f.x + f.y;
            f = upk(a10); float d1 = f.x + f.y;
            f = upk(a11); d1 += f.x + f.y;
            float ag0 = st.y * (d0 - st.x * s1g.x) + bG2.x;
            float ag1 = st.y * (d1 - st.x * s1g.y) + bG2.y;
            float2 oo = *(const float2*)&so[row * 64 + 2 * t];   // per-row g_o
            float g0 = oo.x / (1.f + __expf(-ag0));
            float g1 = oo.y / (1.f + __expf(-ag1));
            *(float2*)&gt[row * 68 + 2 * t] = make_float2(g0, g1);
        }
        __syncwarp();

        // ---- out phase ----
        {
            const ulonglong2* p0 = (const ulonglong2*)(g_WoT + (2 * t) * 64);
            const ulonglong2* p1 = (const ulonglong2*)(g_WoT + (2 * t + 1) * 64);
            #pragma unroll
            for (int i = 0; i < 16; ++i) {
                ulonglong2 v0 = p0[i], v1 = p1[i];
                gw[2 * i] = v0.x; gw[2 * i + 1] = v0.y;
                gw[32 + 2 * i] = v1.x; gw[32 + 2 * i + 1] = v1.y;
            }
        }
        float* Obase = outp + ((size_t)s * RR + r0) * 64;
        for (int row = 0; row < 32; ++row) {
            const ulonglong2* gr = (const ulonglong2*)&gt[row * 68];
            ull a00 = 0ull, a01 = 0ull, a10 = 0ull, a11 = 0ull;
            #pragma unroll
            for (int i = 0; i < 16; ++i) {
                ulonglong2 gv = gr[i];
                a00 = ffma2(gv.x, gw[2 * i], a00);
                a01 = ffma2(gv.y, gw[2 * i + 1], a01);
                a10 = ffma2(gv.x, gw[32 + 2 * i], a10);
                a11 = ffma2(gv.y, gw[32 + 2 * i + 1], a11);
            }
            float2 f;
            f = upk(a00); float d0 = f.x + f.y;
            f = upk(a01); d0 += f.x + f.y;
            f = upk(a10); float d1 = f.x + f.y;
            f = upk(a11); d1 += f.x + f.y;
            float2 xres = *(const float2*)&xt[row * 68 + 2 * t];
            // contiguous 256B store per row, 8KB per tile
            *(float2*)&Obase[row * 64 + 2 * t] =
                make_float2(d0 + bo2.x + xres.x, d1 + bo2.y + xres.y);
        }
        __syncwarp();  // tile reuse barrier before next iteration
    }
}

// ---------------------------------------------------------------------------
extern "C" void kernel_launch(void* const* d_in, const int* in_sizes, int n_in,
                              void* d_out, int out_size)
{
    (void)in_sizes; (void)n_in; (void)out_size;
    const float* M    = (const float*)d_in[0];
    const float* mask = (const float*)d_in[1];
    const float* ln_g = (const float*)d_in[2];
    const float* ln_b = (const float*)d_in[3];
    const float* Wq   = (const float*)d_in[4];
    const float* Wk   = (const float*)d_in[5];
    const float* Wv   = (const float*)d_in[6];
    const float* Wg   = (const float*)d_in[7];
    const float* bg   = (const float*)d_in[8];
    const float* Wo   = (const float*)d_in[9];
    const float* bo   = (const float*)d_in[10];
    float* outp = (float*)d_out;

    const int smemC = (8 * 32 * 68 + 32 * 64) * 4;  // 77824 B
    cudaFuncSetAttribute(kernelC, cudaFuncAttributeMaxDynamicSharedMemorySize, smemC);

    kernelD<<<dim3(12, 64), 256>>>(mask);
    kernelP<<<1, 256>>>(ln_g, ln_b, Wk, Wv, Wg, bg, Wo);
    kernelA<<<dim3(16, 384), 128>>>(M);
    kernelB<<<384, 256>>>(Wq, ln_g, ln_b);
    kernelC<<<dim3(12, 128), 128, smemC>>>(M, bo, outp);
}